// round 3
// baseline (speedup 1.0000x reference)
#include <cuda_runtime.h>
#include <math.h>
#include <stdint.h>

#define NNODES 50000
#define NEDGES 400000
#define HEADS 4
#define CH 128
#define KIN 128
#define NOUT (HEADS * CH)          // 512
#define NH (NNODES * HEADS)        // 200000
#define ETOT (NEDGES + NNODES)     // 450000 (self loops appended)
#define NEG_SLOPE 0.2f

// -------- scratch (static __device__, no allocations allowed) --------
__device__ float g_h[(size_t)NNODES * NOUT];     // 102.4 MB
__device__ float g_asrc[NH];
__device__ float g_adst[NH];
__device__ float g_emax[NH];
__device__ float g_denom[NH];
__device__ float g_eexp[(size_t)ETOT * HEADS];   // 7.2 MB

// ------------------------------------------------------------------
// init: out = bias (atomics accumulate on top), emax = -inf, denom = 0
// ------------------------------------------------------------------
__global__ void init_kernel(float* __restrict__ out, const float* __restrict__ bias) {
    int idx = blockIdx.x * blockDim.x + threadIdx.x;
    if (idx < NH) { g_emax[idx] = -INFINITY; g_denom[idx] = 0.f; }
    if (idx < NNODES * NOUT) out[idx] = bias[idx & (NOUT - 1)];
}

// ------------------------------------------------------------------
// SGEMM: g_h[M=50000, 512] = X[50000,128] @ W[128,512]
// 128x128 block tile, 256 threads, 8x8 per thread, K-chunks of 8,
// double-buffered shared memory.
// ------------------------------------------------------------------
__global__ __launch_bounds__(256) void sgemm_kernel(const float* __restrict__ X,
                                                    const float* __restrict__ W) {
    __shared__ float sA[2][8][132];  // [buf][k][m], padded
    __shared__ float sB[2][8][128];  // [buf][k][n]

    const int bm = blockIdx.x * 128;
    const int bn = blockIdx.y * 128;
    const int tid = threadIdx.x;
    const int tx = tid & 15;         // 0..15 -> 8 cols each
    const int ty = tid >> 4;         // 0..15 -> 8 rows each

    // A load: thread -> (row = tid/2, kcol = (tid&1)*4), float4
    const int a_row = tid >> 1;
    const int a_col = (tid & 1) * 4;
    // B load: thread -> (krow = tid/32, col = (tid&31)*4), float4
    const int b_row = tid >> 5;
    const int b_col = (tid & 31) * 4;

    const bool a_valid = (bm + a_row) < NNODES;
    const float* Aptr = X + (size_t)(bm + a_row) * KIN + a_col;
    const float* Bptr = W + (size_t)b_row * NOUT + bn + b_col;

    float acc[8][8];
#pragma unroll
    for (int i = 0; i < 8; i++)
#pragma unroll
        for (int j = 0; j < 8; j++) acc[i][j] = 0.f;

    float4 ra = a_valid ? *(const float4*)Aptr : make_float4(0.f, 0.f, 0.f, 0.f);
    float4 rb = *(const float4*)Bptr;

    sA[0][a_col + 0][a_row] = ra.x;
    sA[0][a_col + 1][a_row] = ra.y;
    sA[0][a_col + 2][a_row] = ra.z;
    sA[0][a_col + 3][a_row] = ra.w;
    *(float4*)&sB[0][b_row][b_col] = rb;
    __syncthreads();

    const int NCHUNK = KIN / 8;  // 16
#pragma unroll 1
    for (int ch = 0; ch < NCHUNK; ch++) {
        const int cb = ch & 1;
        if (ch < NCHUNK - 1) {
            Aptr += 8;
            Bptr += 8 * NOUT;
            ra = a_valid ? *(const float4*)Aptr : make_float4(0.f, 0.f, 0.f, 0.f);
            rb = *(const float4*)Bptr;
        }
#pragma unroll
        for (int kk = 0; kk < 8; kk++) {
            float ar[8], br[8];
            *(float4*)&ar[0] = *(const float4*)&sA[cb][kk][ty * 8];
            *(float4*)&ar[4] = *(const float4*)&sA[cb][kk][ty * 8 + 4];
            *(float4*)&br[0] = *(const float4*)&sB[cb][kk][tx * 8];
            *(float4*)&br[4] = *(const float4*)&sB[cb][kk][tx * 8 + 4];
#pragma unroll
            for (int i = 0; i < 8; i++)
#pragma unroll
                for (int j = 0; j < 8; j++) acc[i][j] = fmaf(ar[i], br[j], acc[i][j]);
        }
        if (ch < NCHUNK - 1) {
            const int nb = cb ^ 1;
            sA[nb][a_col + 0][a_row] = ra.x;
            sA[nb][a_col + 1][a_row] = ra.y;
            sA[nb][a_col + 2][a_row] = ra.z;
            sA[nb][a_col + 3][a_row] = ra.w;
            *(float4*)&sB[nb][b_row][b_col] = rb;
            __syncthreads();
        }
    }

    // epilogue: store 8x8 tile
#pragma unroll
    for (int i = 0; i < 8; i++) {
        const int r = bm + ty * 8 + i;
        if (r < NNODES) {
            float* dst = &g_h[(size_t)r * NOUT + bn + tx * 8];
            *(float4*)dst       = make_float4(acc[i][0], acc[i][1], acc[i][2], acc[i][3]);
            *(float4*)(dst + 4) = make_float4(acc[i][4], acc[i][5], acc[i][6], acc[i][7]);
        }
    }
}

// ------------------------------------------------------------------
// attention scores: one warp per (node, head)
// ------------------------------------------------------------------
__global__ __launch_bounds__(256) void attn_scores_kernel(const float* __restrict__ att_src,
                                                          const float* __restrict__ att_dst) {
    const int gw = (blockIdx.x * blockDim.x + threadIdx.x) >> 5;
    const int lane = threadIdx.x & 31;
    if (gw >= NH) return;
    const int n = gw >> 2;
    const int hd = gw & 3;

    const float4 hv = *(const float4*)&g_h[(size_t)n * NOUT + hd * CH + lane * 4];
    const float4 as = *(const float4*)&att_src[hd * CH + lane * 4];
    const float4 ad = *(const float4*)&att_dst[hd * CH + lane * 4];
    float s = hv.x * as.x + hv.y * as.y + hv.z * as.z + hv.w * as.w;
    float d = hv.x * ad.x + hv.y * ad.y + hv.z * ad.z + hv.w * ad.w;
#pragma unroll
    for (int o = 16; o; o >>= 1) {
        s += __shfl_xor_sync(0xffffffffu, s, o);
        d += __shfl_xor_sync(0xffffffffu, d, o);
    }
    if (lane == 0) {
        g_asrc[gw] = s;
        g_adst[gw] = d;
    }
}

// ------------------------------------------------------------------
// float atomic max via signed/unsigned int ordering trick
// ------------------------------------------------------------------
__device__ __forceinline__ void atomicMaxF(float* addr, float v) {
    if (v >= 0.f)
        atomicMax((int*)addr, __float_as_int(v));
    else
        atomicMin((unsigned int*)addr, __float_as_uint(v));
}

// edge_index is int32 on device (harness stores int32; layout [2, E] row-major)
__device__ __forceinline__ void edge_src_dst(const int* __restrict__ ei, int e,
                                             int& src, int& dst) {
    if (e < NEDGES) {
        src = ei[e];
        dst = ei[NEDGES + e];
    } else {
        src = dst = e - NEDGES;  // self loop
    }
}

__device__ __forceinline__ float lrelu(float v) { return v > 0.f ? v : NEG_SLOPE * v; }

// ------------------------------------------------------------------
// pass 1: scatter-max of leakyrelu(a_src[src] + a_dst[dst]) into e_max[dst]
// ------------------------------------------------------------------
__global__ __launch_bounds__(256) void edge_max_kernel(const int* __restrict__ ei) {
    const int e = blockIdx.x * blockDim.x + threadIdx.x;
    if (e >= ETOT) return;
    int src, dst;
    edge_src_dst(ei, e, src, dst);
    const float4 as = *(const float4*)&g_asrc[src * 4];
    const float4 ad = *(const float4*)&g_adst[dst * 4];
    atomicMaxF(&g_emax[dst * 4 + 0], lrelu(as.x + ad.x));
    atomicMaxF(&g_emax[dst * 4 + 1], lrelu(as.y + ad.y));
    atomicMaxF(&g_emax[dst * 4 + 2], lrelu(as.z + ad.z));
    atomicMaxF(&g_emax[dst * 4 + 3], lrelu(as.w + ad.w));
}

// ------------------------------------------------------------------
// pass 2: e_exp = exp(e - e_max[dst]); denom[dst] += e_exp (atomic)
// ------------------------------------------------------------------
__global__ __launch_bounds__(256) void edge_exp_kernel(const int* __restrict__ ei) {
    const int e = blockIdx.x * blockDim.x + threadIdx.x;
    if (e >= ETOT) return;
    int src, dst;
    edge_src_dst(ei, e, src, dst);
    const float4 as = *(const float4*)&g_asrc[src * 4];
    const float4 ad = *(const float4*)&g_adst[dst * 4];
    const float4 em = *(const float4*)&g_emax[dst * 4];
    float e0 = expf(lrelu(as.x + ad.x) - em.x);
    float e1 = expf(lrelu(as.y + ad.y) - em.y);
    float e2 = expf(lrelu(as.z + ad.z) - em.z);
    float e3 = expf(lrelu(as.w + ad.w) - em.w);
    *(float4*)&g_eexp[(size_t)e * 4] = make_float4(e0, e1, e2, e3);
    atomicAdd(&g_denom[dst * 4 + 0], e0);
    atomicAdd(&g_denom[dst * 4 + 1], e1);
    atomicAdd(&g_denom[dst * 4 + 2], e2);
    atomicAdd(&g_denom[dst * 4 + 3], e3);
}

// ------------------------------------------------------------------
// aggregation: out[dst] += alpha * h[src]; one block (128 thr) per edge,
// warp w handles head w; vectorized global reductions (16B).
// ------------------------------------------------------------------
__global__ __launch_bounds__(128) void aggregate_kernel(const int* __restrict__ ei,
                                                        float* __restrict__ out) {
    const int e = blockIdx.x;
    const int hd = threadIdx.x >> 5;
    const int lane = threadIdx.x & 31;
    int src, dst;
    edge_src_dst(ei, e, src, dst);

    float alpha = 0.f;
    if (lane == 0) alpha = g_eexp[(size_t)e * 4 + hd] / g_denom[dst * 4 + hd];
    alpha = __shfl_sync(0xffffffffu, alpha, 0);

    const float4 hv = *(const float4*)&g_h[(size_t)src * NOUT + hd * CH + lane * 4];
    float* op = &out[(size_t)dst * NOUT + hd * CH + lane * 4];
    asm volatile("red.global.add.v4.f32 [%0], {%1, %2, %3, %4};" ::"l"(op),
                 "f"(hv.x * alpha), "f"(hv.y * alpha), "f"(hv.z * alpha), "f"(hv.w * alpha)
                 : "memory");
}

// ------------------------------------------------------------------
extern "C" void kernel_launch(void* const* d_in, const int* in_sizes, int n_in,
                              void* d_out, int out_size) {
    const float* x        = (const float*)d_in[0];
    const int* ei         = (const int*)d_in[1];
    const float* W        = (const float*)d_in[2];
    const float* att_src  = (const float*)d_in[3];
    const float* att_dst  = (const float*)d_in[4];
    const float* bias     = (const float*)d_in[5];
    float* out            = (float*)d_out;

    (void)in_sizes; (void)n_in; (void)out_size;

    // init out=bias, emax=-inf, denom=0
    {
        int total = NNODES * NOUT;
        init_kernel<<<(total + 255) / 256, 256>>>(out, bias);
    }
    // h = x @ W
    {
        dim3 grid((NNODES + 127) / 128, NOUT / 128);
        sgemm_kernel<<<grid, 256>>>(x, W);
    }
    // per-(node,head) attention scores
    {
        int threads = NH * 32;
        attn_scores_kernel<<<(threads + 255) / 256, 256>>>(att_src, att_dst);
    }
    // softmax passes
    edge_max_kernel<<<(ETOT + 255) / 256, 256>>>(ei);
    edge_exp_kernel<<<(ETOT + 255) / 256, 256>>>(ei);
    // weighted aggregation
    aggregate_kernel<<<ETOT, 128>>>(ei, out);
}

// round 4
// speedup vs baseline: 1.2915x; 1.2915x over previous
#include <cuda_runtime.h>
#include <math.h>
#include <stdint.h>

#define NNODES 50000
#define NEDGES 400000
#define HEADS 4
#define CH 128
#define KIN 128
#define NOUT (HEADS * CH)          // 512
#define NH (NNODES * HEADS)        // 200000
#define ETOT (NEDGES + NNODES)     // 450000 (self loops appended)
#define NEG_SLOPE 0.2f
#define CAP 1024                   // smem-cached edges per dst (fallback beyond)

// -------- scratch (static __device__, no allocations allowed) --------
__device__ float g_h[(size_t)NNODES * NOUT];     // 102.4 MB
__device__ float g_asrc[NH];
__device__ float g_adst[NH];
__device__ int   g_deg[NNODES];
__device__ int   g_start[NNODES + 1];
__device__ int   g_work[NNODES];
__device__ int   g_csr[ETOT];                    // stores src per CSR slot

__device__ __forceinline__ float lrelu(float v) { return v > 0.f ? v : NEG_SLOPE * v; }

// ------------------------------------------------------------------
// zero degree counters (must happen every call: graph replays)
// ------------------------------------------------------------------
__global__ void zero_kernel() {
    int i = blockIdx.x * blockDim.x + threadIdx.x;
    if (i < NNODES) g_deg[i] = 0;
}

// ------------------------------------------------------------------
// SGEMM: g_h = X @ W, with fused attention-score epilogue.
// Block tile 128x128 = one head (CH==128), 256 threads, 8x8/thread.
// ------------------------------------------------------------------
__global__ __launch_bounds__(256) void sgemm_kernel(const float* __restrict__ X,
                                                    const float* __restrict__ W,
                                                    const float* __restrict__ att_src,
                                                    const float* __restrict__ att_dst) {
    __shared__ float sA[2][8][132];
    __shared__ float sB[2][8][128];

    const int bm = blockIdx.x * 128;
    const int head = blockIdx.y;          // bn = head*128
    const int bn = head * 128;
    const int tid = threadIdx.x;
    const int tx = tid & 15;
    const int ty = tid >> 4;

    const int a_row = tid >> 1;
    const int a_col = (tid & 1) * 4;
    const int b_row = tid >> 5;
    const int b_col = (tid & 31) * 4;

    const bool a_valid = (bm + a_row) < NNODES;
    const float* Aptr = X + (size_t)(bm + a_row) * KIN + a_col;
    const float* Bptr = W + (size_t)b_row * NOUT + bn + b_col;

    float acc[8][8];
#pragma unroll
    for (int i = 0; i < 8; i++)
#pragma unroll
        for (int j = 0; j < 8; j++) acc[i][j] = 0.f;

    float4 ra = a_valid ? *(const float4*)Aptr : make_float4(0.f, 0.f, 0.f, 0.f);
    float4 rb = *(const float4*)Bptr;

    sA[0][a_col + 0][a_row] = ra.x;
    sA[0][a_col + 1][a_row] = ra.y;
    sA[0][a_col + 2][a_row] = ra.z;
    sA[0][a_col + 3][a_row] = ra.w;
    *(float4*)&sB[0][b_row][b_col] = rb;
    __syncthreads();

    const int NCHUNK = KIN / 8;  // 16
#pragma unroll 1
    for (int ch = 0; ch < NCHUNK; ch++) {
        const int cb = ch & 1;
        if (ch < NCHUNK - 1) {
            Aptr += 8;
            Bptr += 8 * NOUT;
            ra = a_valid ? *(const float4*)Aptr : make_float4(0.f, 0.f, 0.f, 0.f);
            rb = *(const float4*)Bptr;
        }
#pragma unroll
        for (int kk = 0; kk < 8; kk++) {
            float ar[8], br[8];
            *(float4*)&ar[0] = *(const float4*)&sA[cb][kk][ty * 8];
            *(float4*)&ar[4] = *(const float4*)&sA[cb][kk][ty * 8 + 4];
            *(float4*)&br[0] = *(const float4*)&sB[cb][kk][tx * 8];
            *(float4*)&br[4] = *(const float4*)&sB[cb][kk][tx * 8 + 4];
#pragma unroll
            for (int i = 0; i < 8; i++)
#pragma unroll
                for (int j = 0; j < 8; j++) acc[i][j] = fmaf(ar[i], br[j], acc[i][j]);
        }
        if (ch < NCHUNK - 1) {
            const int nb = cb ^ 1;
            sA[nb][a_col + 0][a_row] = ra.x;
            sA[nb][a_col + 1][a_row] = ra.y;
            sA[nb][a_col + 2][a_row] = ra.z;
            sA[nb][a_col + 3][a_row] = ra.w;
            *(float4*)&sB[nb][b_row][b_col] = rb;
            __syncthreads();
        }
    }

    // load att vectors for this thread's 8 columns
    float as_r[8], ad_r[8];
#pragma unroll
    for (int j = 0; j < 8; j++) {
        as_r[j] = __ldg(&att_src[head * CH + tx * 8 + j]);
        ad_r[j] = __ldg(&att_dst[head * CH + tx * 8 + j]);
    }

    // epilogue: store 8x8 tile + fused score partial reduction
#pragma unroll
    for (int i = 0; i < 8; i++) {
        const int r = bm + ty * 8 + i;
        float s = 0.f, d = 0.f;
#pragma unroll
        for (int j = 0; j < 8; j++) {
            s = fmaf(acc[i][j], as_r[j], s);
            d = fmaf(acc[i][j], ad_r[j], d);
        }
        // half-warp reduce over tx (lanes 0-15 / 16-31 share a ty)
#pragma unroll
        for (int o = 8; o; o >>= 1) {
            s += __shfl_xor_sync(0xffffffffu, s, o);
            d += __shfl_xor_sync(0xffffffffu, d, o);
        }
        if (r < NNODES) {
            float* dstp = &g_h[(size_t)r * NOUT + bn + tx * 8];
            *(float4*)dstp       = make_float4(acc[i][0], acc[i][1], acc[i][2], acc[i][3]);
            *(float4*)(dstp + 4) = make_float4(acc[i][4], acc[i][5], acc[i][6], acc[i][7]);
            if ((tid & 15) == 0) {
                g_asrc[r * 4 + head] = s;
                g_adst[r * 4 + head] = d;
            }
        }
    }
}

// ------------------------------------------------------------------
// CSR build: histogram -> single-block scan -> scatter
// ------------------------------------------------------------------
__global__ __launch_bounds__(256) void hist_kernel(const int* __restrict__ ei) {
    const int e = blockIdx.x * blockDim.x + threadIdx.x;
    if (e >= ETOT) return;
    const int dst = (e < NEDGES) ? ei[NEDGES + e] : (e - NEDGES);
    atomicAdd(&g_deg[dst], 1);
}

__global__ __launch_bounds__(1024) void scan_kernel() {
    __shared__ int partial[1024];
    const int tid = threadIdx.x;
    const int CHUNK = (NNODES + 1023) / 1024;  // 49
    const int base = tid * CHUNK;

    int s = 0;
    for (int i = 0; i < CHUNK; i++) {
        int idx = base + i;
        if (idx < NNODES) s += g_deg[idx];
    }
    partial[tid] = s;
    __syncthreads();
    // Hillis-Steele inclusive scan
    for (int off = 1; off < 1024; off <<= 1) {
        int v = (tid >= off) ? partial[tid - off] : 0;
        __syncthreads();
        partial[tid] += v;
        __syncthreads();
    }
    int run = partial[tid] - s;  // exclusive prefix of this chunk
    for (int i = 0; i < CHUNK; i++) {
        int idx = base + i;
        if (idx < NNODES) {
            int d = g_deg[idx];
            g_start[idx] = run;
            g_work[idx] = run;
            run += d;
        }
    }
    if (tid == 1023) g_start[NNODES] = run;
}

__global__ __launch_bounds__(256) void scatter_kernel(const int* __restrict__ ei) {
    const int e = blockIdx.x * blockDim.x + threadIdx.x;
    if (e >= ETOT) return;
    int src, dst;
    if (e < NEDGES) {
        src = ei[e];
        dst = ei[NEDGES + e];
    } else {
        src = dst = e - NEDGES;
    }
    const int pos = atomicAdd(&g_work[dst], 1);
    g_csr[pos] = src;
}

// ------------------------------------------------------------------
// fused per-dst softmax + aggregation. One block / dst node.
// 128 threads: warp = head, lane*4 = channel offset.
// ------------------------------------------------------------------
__global__ __launch_bounds__(128) void aggregate_kernel(const float* __restrict__ bias,
                                                        float* __restrict__ out) {
    __shared__ float4 s_sc[CAP];
    __shared__ int    s_src[CAP];
    __shared__ float4 s_red[4];
    __shared__ float4 s_bcast;

    const int dst = blockIdx.x;
    const int tid = threadIdx.x;
    const int lane = tid & 31;
    const int warp = tid >> 5;  // = head

    const int start = g_start[dst];
    const int deg = g_start[dst + 1] - start;
    const float4 ad = *(const float4*)&g_adst[dst * 4];

    // ---- phase 1: scores + per-thread max (cache scores/src in smem) ----
    float4 mx = make_float4(-INFINITY, -INFINITY, -INFINITY, -INFINITY);
    for (int i = tid; i < deg; i += 128) {
        const int src = g_csr[start + i];
        const float4 as = *(const float4*)&g_asrc[src * 4];
        float4 sc;
        sc.x = lrelu(as.x + ad.x);
        sc.y = lrelu(as.y + ad.y);
        sc.z = lrelu(as.z + ad.z);
        sc.w = lrelu(as.w + ad.w);
        if (i < CAP) { s_sc[i] = sc; s_src[i] = src; }
        mx.x = fmaxf(mx.x, sc.x);
        mx.y = fmaxf(mx.y, sc.y);
        mx.z = fmaxf(mx.z, sc.z);
        mx.w = fmaxf(mx.w, sc.w);
    }
#pragma unroll
    for (int o = 16; o; o >>= 1) {
        mx.x = fmaxf(mx.x, __shfl_xor_sync(0xffffffffu, mx.x, o));
        mx.y = fmaxf(mx.y, __shfl_xor_sync(0xffffffffu, mx.y, o));
        mx.z = fmaxf(mx.z, __shfl_xor_sync(0xffffffffu, mx.z, o));
        mx.w = fmaxf(mx.w, __shfl_xor_sync(0xffffffffu, mx.w, o));
    }
    if (lane == 0) s_red[warp] = mx;
    __syncthreads();
    if (tid == 0) {
        float4 m = s_red[0];
#pragma unroll
        for (int w = 1; w < 4; w++) {
            m.x = fmaxf(m.x, s_red[w].x);
            m.y = fmaxf(m.y, s_red[w].y);
            m.z = fmaxf(m.z, s_red[w].z);
            m.w = fmaxf(m.w, s_red[w].w);
        }
        s_bcast = m;
    }
    __syncthreads();
    const float4 m = s_bcast;

    // ---- phase 2: exp + sum ----
    float4 sum = make_float4(0.f, 0.f, 0.f, 0.f);
    for (int i = tid; i < deg; i += 128) {
        float4 sc;
        if (i < CAP) {
            sc = s_sc[i];  // written by this same thread in phase 1
        } else {
            const int src = g_csr[start + i];
            const float4 as = *(const float4*)&g_asrc[src * 4];
            sc.x = lrelu(as.x + ad.x);
            sc.y = lrelu(as.y + ad.y);
            sc.z = lrelu(as.z + ad.z);
            sc.w = lrelu(as.w + ad.w);
        }
        float4 e;
        e.x = __expf(sc.x - m.x);
        e.y = __expf(sc.y - m.y);
        e.z = __expf(sc.z - m.z);
        e.w = __expf(sc.w - m.w);
        if (i < CAP) s_sc[i] = e;
        sum.x += e.x; sum.y += e.y; sum.z += e.z; sum.w += e.w;
    }
#pragma unroll
    for (int o = 16; o; o >>= 1) {
        sum.x += __shfl_xor_sync(0xffffffffu, sum.x, o);
        sum.y += __shfl_xor_sync(0xffffffffu, sum.y, o);
        sum.z += __shfl_xor_sync(0xffffffffu, sum.z, o);
        sum.w += __shfl_xor_sync(0xffffffffu, sum.w, o);
    }
    __syncthreads();   // protect s_red reuse + ensure phase-2 s_sc writes visible
    if (lane == 0) s_red[warp] = sum;
    __syncthreads();
    if (tid == 0) {
        float4 t = s_red[0];
#pragma unroll
        for (int w = 1; w < 4; w++) {
            t.x += s_red[w].x; t.y += s_red[w].y; t.z += s_red[w].z; t.w += s_red[w].w;
        }
        s_bcast = t;
    }
    __syncthreads();
    const float4 dn = s_bcast;

    // ---- phase 3: aggregate. warp=head, lane owns 4 channels ----
    const int hd = warp;
    const int c0 = lane * 4;
    const float denh = (hd == 0) ? dn.x : (hd == 1) ? dn.y : (hd == 2) ? dn.z : dn.w;
    const float mh   = (hd == 0) ? m.x  : (hd == 1) ? m.y  : (hd == 2) ? m.z  : m.w;
    const float adh  = (hd == 0) ? ad.x : (hd == 1) ? ad.y : (hd == 2) ? ad.z : ad.w;
    const float invd = 1.0f / denh;

    float4 acc = make_float4(0.f, 0.f, 0.f, 0.f);
    for (int i = 0; i < deg; i++) {
        float e;
        int src;
        if (i < CAP) {
            const float4 t = s_sc[i];
            e = (hd == 0) ? t.x : (hd == 1) ? t.y : (hd == 2) ? t.z : t.w;
            src = s_src[i];
        } else {
            src = g_csr[start + i];
            const float a_s = g_asrc[src * 4 + hd];
            e = __expf(lrelu(a_s + adh) - mh);
        }
        const float al = e * invd;
        const float4 hv = *(const float4*)&g_h[(size_t)src * NOUT + hd * CH + c0];
        acc.x = fmaf(al, hv.x, acc.x);
        acc.y = fmaf(al, hv.y, acc.y);
        acc.z = fmaf(al, hv.z, acc.z);
        acc.w = fmaf(al, hv.w, acc.w);
    }
    const float4 b = *(const float4*)&bias[hd * CH + c0];
    acc.x += b.x; acc.y += b.y; acc.z += b.z; acc.w += b.w;
    *(float4*)&out[(size_t)dst * NOUT + hd * CH + c0] = acc;
}

// ------------------------------------------------------------------
extern "C" void kernel_launch(void* const* d_in, const int* in_sizes, int n_in,
                              void* d_out, int out_size) {
    const float* x       = (const float*)d_in[0];
    const int* ei        = (const int*)d_in[1];
    const float* W       = (const float*)d_in[2];
    const float* att_src = (const float*)d_in[3];
    const float* att_dst = (const float*)d_in[4];
    const float* bias    = (const float*)d_in[5];
    float* out           = (float*)d_out;

    (void)in_sizes; (void)n_in; (void)out_size;

    zero_kernel<<<(NNODES + 255) / 256, 256>>>();
    {
        dim3 grid((NNODES + 127) / 128, HEADS);
        sgemm_kernel<<<grid, 256>>>(x, W, att_src, att_dst);
    }
    hist_kernel<<<(ETOT + 255) / 256, 256>>>(ei);
    scan_kernel<<<1, 1024>>>();
    scatter_kernel<<<(ETOT + 255) / 256, 256>>>(ei);
    aggregate_kernel<<<NNODES, 128>>>(bias, out);
}

// round 5
// speedup vs baseline: 1.7638x; 1.3657x over previous
#include <cuda_runtime.h>
#include <math.h>
#include <stdint.h>

#define NNODES 50000
#define NEDGES 400000
#define HEADS 4
#define CH 128
#define KIN 128
#define NOUT (HEADS * CH)          // 512
#define NH (NNODES * HEADS)        // 200000
#define ETOT (NEDGES + NNODES)     // 450000 (self loops appended)
#define NEG_SLOPE 0.2f

// -------- scratch (static __device__, no allocations allowed) --------
__device__ float g_h[(size_t)NNODES * NOUT];     // 102.4 MB
__device__ float g_asrc[NH];
__device__ float g_adst[NH];
__device__ float g_rden[NH];                     // reciprocal softmax denom
__device__ float g_eexp[(size_t)ETOT * HEADS];   // unnormalized exp per edge
__device__ int   g_deg[NNODES];
__device__ int   g_start[NNODES];
__device__ int   g_work[NNODES];
__device__ int   g_csr[ETOT];                    // src per CSR slot
__device__ int   g_total;

__device__ __forceinline__ float lrelu(float v) { return v > 0.f ? v : NEG_SLOPE * v; }

// ------------------------------------------------------------------
__global__ void zero_kernel() {
    int i = blockIdx.x * blockDim.x + threadIdx.x;
    if (i < NNODES) g_deg[i] = 0;
    if (i == 0) g_total = 0;
}

// ------------------------------------------------------------------
// SGEMM: g_h = X @ W, fused attention-score epilogue.
// Block tile 128x128 = one head, 256 threads, 8x8/thread, double-buffered.
// ------------------------------------------------------------------
__global__ __launch_bounds__(256) void sgemm_kernel(const float* __restrict__ X,
                                                    const float* __restrict__ W,
                                                    const float* __restrict__ att_src,
                                                    const float* __restrict__ att_dst) {
    __shared__ float sA[2][8][132];
    __shared__ float sB[2][8][128];

    const int bm = blockIdx.x * 128;
    const int head = blockIdx.y;
    const int bn = head * 128;
    const int tid = threadIdx.x;
    const int tx = tid & 15;
    const int ty = tid >> 4;

    const int a_row = tid >> 1;
    const int a_col = (tid & 1) * 4;
    const int b_row = tid >> 5;
    const int b_col = (tid & 31) * 4;

    const bool a_valid = (bm + a_row) < NNODES;
    const float* Aptr = X + (size_t)(bm + a_row) * KIN + a_col;
    const float* Bptr = W + (size_t)b_row * NOUT + bn + b_col;

    float acc[8][8];
#pragma unroll
    for (int i = 0; i < 8; i++)
#pragma unroll
        for (int j = 0; j < 8; j++) acc[i][j] = 0.f;

    float4 ra = a_valid ? *(const float4*)Aptr : make_float4(0.f, 0.f, 0.f, 0.f);
    float4 rb = *(const float4*)Bptr;

    sA[0][a_col + 0][a_row] = ra.x;
    sA[0][a_col + 1][a_row] = ra.y;
    sA[0][a_col + 2][a_row] = ra.z;
    sA[0][a_col + 3][a_row] = ra.w;
    *(float4*)&sB[0][b_row][b_col] = rb;
    __syncthreads();

    const int NCHUNK = KIN / 8;  // 16
#pragma unroll 1
    for (int ch = 0; ch < NCHUNK; ch++) {
        const int cb = ch & 1;
        if (ch < NCHUNK - 1) {
            Aptr += 8;
            Bptr += 8 * NOUT;
            ra = a_valid ? *(const float4*)Aptr : make_float4(0.f, 0.f, 0.f, 0.f);
            rb = *(const float4*)Bptr;
        }
#pragma unroll
        for (int kk = 0; kk < 8; kk++) {
            float ar[8], br[8];
            *(float4*)&ar[0] = *(const float4*)&sA[cb][kk][ty * 8];
            *(float4*)&ar[4] = *(const float4*)&sA[cb][kk][ty * 8 + 4];
            *(float4*)&br[0] = *(const float4*)&sB[cb][kk][tx * 8];
            *(float4*)&br[4] = *(const float4*)&sB[cb][kk][tx * 8 + 4];
#pragma unroll
            for (int i = 0; i < 8; i++)
#pragma unroll
                for (int j = 0; j < 8; j++) acc[i][j] = fmaf(ar[i], br[j], acc[i][j]);
        }
        if (ch < NCHUNK - 1) {
            const int nb = cb ^ 1;
            sA[nb][a_col + 0][a_row] = ra.x;
            sA[nb][a_col + 1][a_row] = ra.y;
            sA[nb][a_col + 2][a_row] = ra.z;
            sA[nb][a_col + 3][a_row] = ra.w;
            *(float4*)&sB[nb][b_row][b_col] = rb;
            __syncthreads();
        }
    }

    float as_r[8], ad_r[8];
#pragma unroll
    for (int j = 0; j < 8; j++) {
        as_r[j] = __ldg(&att_src[head * CH + tx * 8 + j]);
        ad_r[j] = __ldg(&att_dst[head * CH + tx * 8 + j]);
    }

#pragma unroll
    for (int i = 0; i < 8; i++) {
        const int r = bm + ty * 8 + i;
        float s = 0.f, d = 0.f;
#pragma unroll
        for (int j = 0; j < 8; j++) {
            s = fmaf(acc[i][j], as_r[j], s);
            d = fmaf(acc[i][j], ad_r[j], d);
        }
#pragma unroll
        for (int o = 8; o; o >>= 1) {
            s += __shfl_xor_sync(0xffffffffu, s, o);
            d += __shfl_xor_sync(0xffffffffu, d, o);
        }
        if (r < NNODES) {
            float* dstp = &g_h[(size_t)r * NOUT + bn + tx * 8];
            *(float4*)dstp       = make_float4(acc[i][0], acc[i][1], acc[i][2], acc[i][3]);
            *(float4*)(dstp + 4) = make_float4(acc[i][4], acc[i][5], acc[i][6], acc[i][7]);
            if ((tid & 15) == 0) {
                g_asrc[r * 4 + head] = s;
                g_adst[r * 4 + head] = d;
            }
        }
    }
}

// ------------------------------------------------------------------
// CSR build: histogram -> hierarchical scan (atomic block base) -> scatter
// ------------------------------------------------------------------
__global__ __launch_bounds__(256) void hist_kernel(const int* __restrict__ ei) {
    const int e = blockIdx.x * blockDim.x + threadIdx.x;
    if (e >= ETOT) return;
    const int dst = (e < NEDGES) ? ei[NEDGES + e] : (e - NEDGES);
    atomicAdd(&g_deg[dst], 1);
}

__global__ __launch_bounds__(256) void scan_kernel() {
    __shared__ int wsum[8];
    __shared__ int s_base;
    const int tid = threadIdx.x;
    const int lane = tid & 31;
    const int warp = tid >> 5;
    const int i = blockIdx.x * 256 + tid;

    const int d = (i < NNODES) ? g_deg[i] : 0;
    // warp inclusive scan
    int v = d;
#pragma unroll
    for (int o = 1; o < 32; o <<= 1) {
        int t = __shfl_up_sync(0xffffffffu, v, o);
        if (lane >= o) v += t;
    }
    if (lane == 31) wsum[warp] = v;
    __syncthreads();
    if (tid == 0) {
        int run = 0;
#pragma unroll
        for (int w = 0; w < 8; w++) {
            int t = wsum[w];
            wsum[w] = run;
            run += t;
        }
        s_base = atomicAdd(&g_total, run);  // claim block's segment base
    }
    __syncthreads();
    if (i < NNODES) {
        const int excl = s_base + wsum[warp] + v - d;
        g_start[i] = excl;
        g_work[i] = excl;
    }
}

__global__ __launch_bounds__(256) void scatter_kernel(const int* __restrict__ ei) {
    const int e = blockIdx.x * blockDim.x + threadIdx.x;
    if (e >= ETOT) return;
    int src, dst;
    if (e < NEDGES) {
        src = ei[e];
        dst = ei[NEDGES + e];
    } else {
        src = dst = e - NEDGES;
    }
    const int pos = atomicAdd(&g_work[dst], 1);
    g_csr[pos] = src;
}

// ------------------------------------------------------------------
// softmax: one warp per dst node, all 4 heads at once.
// Writes unnormalized exp per edge (g_eexp) + reciprocal denom (g_rden).
// ------------------------------------------------------------------
__global__ __launch_bounds__(256) void softmax_kernel() {
    const int gw = blockIdx.x * 8 + (threadIdx.x >> 5);
    const int lane = threadIdx.x & 31;
    if (gw >= NNODES) return;

    const int start = g_start[gw];
    const int deg = g_deg[gw];
    const float4 ad = *(const float4*)&g_adst[gw * 4];

    // pass 1: max
    float4 mx = make_float4(-INFINITY, -INFINITY, -INFINITY, -INFINITY);
    for (int i = lane; i < deg; i += 32) {
        const int src = g_csr[start + i];
        const float4 as = *(const float4*)&g_asrc[src * 4];
        mx.x = fmaxf(mx.x, lrelu(as.x + ad.x));
        mx.y = fmaxf(mx.y, lrelu(as.y + ad.y));
        mx.z = fmaxf(mx.z, lrelu(as.z + ad.z));
        mx.w = fmaxf(mx.w, lrelu(as.w + ad.w));
    }
#pragma unroll
    for (int o = 16; o; o >>= 1) {
        mx.x = fmaxf(mx.x, __shfl_xor_sync(0xffffffffu, mx.x, o));
        mx.y = fmaxf(mx.y, __shfl_xor_sync(0xffffffffu, mx.y, o));
        mx.z = fmaxf(mx.z, __shfl_xor_sync(0xffffffffu, mx.z, o));
        mx.w = fmaxf(mx.w, __shfl_xor_sync(0xffffffffu, mx.w, o));
    }

    // pass 2: exp (store) + sum
    float4 sm = make_float4(0.f, 0.f, 0.f, 0.f);
    for (int i = lane; i < deg; i += 32) {
        const int src = g_csr[start + i];
        const float4 as = *(const float4*)&g_asrc[src * 4];
        float4 e;
        e.x = __expf(lrelu(as.x + ad.x) - mx.x);
        e.y = __expf(lrelu(as.y + ad.y) - mx.y);
        e.z = __expf(lrelu(as.z + ad.z) - mx.z);
        e.w = __expf(lrelu(as.w + ad.w) - mx.w);
        *(float4*)&g_eexp[(size_t)(start + i) * 4] = e;
        sm.x += e.x; sm.y += e.y; sm.z += e.z; sm.w += e.w;
    }
#pragma unroll
    for (int o = 16; o; o >>= 1) {
        sm.x += __shfl_xor_sync(0xffffffffu, sm.x, o);
        sm.y += __shfl_xor_sync(0xffffffffu, sm.y, o);
        sm.z += __shfl_xor_sync(0xffffffffu, sm.z, o);
        sm.w += __shfl_xor_sync(0xffffffffu, sm.w, o);
    }
    if (lane == 0) {
        float4 r;
        r.x = 1.0f / sm.x; r.y = 1.0f / sm.y; r.z = 1.0f / sm.z; r.w = 1.0f / sm.w;
        *(float4*)&g_rden[gw * 4] = r;
    }
}

// ------------------------------------------------------------------
// aggregation: one warp per (dst, head). Edge indices/alphas batched
// one-per-lane then shuffled; inner loop = coalesced 512B h row + FMA.
// ------------------------------------------------------------------
__global__ __launch_bounds__(256) void aggregate_kernel(const float* __restrict__ bias,
                                                        float* __restrict__ out) {
    const int gw = blockIdx.x * 8 + (threadIdx.x >> 5);
    const int lane = threadIdx.x & 31;
    if (gw >= NH) return;
    const int dst = gw >> 2;
    const int hd = gw & 3;

    const int start = g_start[dst];
    const int deg = g_deg[dst];
    const float invd = g_rden[dst * 4 + hd];

    float4 acc = make_float4(0.f, 0.f, 0.f, 0.f);
    for (int base = 0; base < deg; base += 32) {
        const int n = min(32, deg - base);
        int src_l = 0;
        float e_l = 0.f;
        if (lane < n) {
            src_l = g_csr[start + base + lane];
            e_l = g_eexp[(size_t)(start + base + lane) * 4 + hd];
        }
        for (int j = 0; j < n; j++) {
            const int src = __shfl_sync(0xffffffffu, src_l, j);
            const float al = __shfl_sync(0xffffffffu, e_l, j) * invd;
            const float4 hv = *(const float4*)&g_h[(size_t)src * NOUT + hd * CH + lane * 4];
            acc.x = fmaf(al, hv.x, acc.x);
            acc.y = fmaf(al, hv.y, acc.y);
            acc.z = fmaf(al, hv.z, acc.z);
            acc.w = fmaf(al, hv.w, acc.w);
        }
    }
    const float4 b = *(const float4*)&bias[hd * CH + lane * 4];
    acc.x += b.x; acc.y += b.y; acc.z += b.z; acc.w += b.w;
    *(float4*)&out[(size_t)dst * NOUT + hd * CH + lane * 4] = acc;
}

// ------------------------------------------------------------------
extern "C" void kernel_launch(void* const* d_in, const int* in_sizes, int n_in,
                              void* d_out, int out_size) {
    const float* x       = (const float*)d_in[0];
    const int* ei        = (const int*)d_in[1];
    const float* W       = (const float*)d_in[2];
    const float* att_src = (const float*)d_in[3];
    const float* att_dst = (const float*)d_in[4];
    const float* bias    = (const float*)d_in[5];
    float* out           = (float*)d_out;

    (void)in_sizes; (void)n_in; (void)out_size;

    zero_kernel<<<(NNODES + 255) / 256, 256>>>();
    {
        dim3 grid((NNODES + 127) / 128, HEADS);
        sgemm_kernel<<<grid, 256>>>(x, W, att_src, att_dst);
    }
    hist_kernel<<<(ETOT + 255) / 256, 256>>>(ei);
    scan_kernel<<<(NNODES + 255) / 256, 256>>>();
    scatter_kernel<<<(ETOT + 255) / 256, 256>>>(ei);
    softmax_kernel<<<(NNODES + 7) / 8, 256>>>();
    aggregate_kernel<<<(NH + 7) / 8, 256>>>(bias, out);
}

// round 8
// speedup vs baseline: 2.6019x; 1.4752x over previous
#include <cuda_runtime.h>
#include <math.h>
#include <stdint.h>

#define NNODES 50000
#define NEDGES 400000
#define HEADS 4
#define CH 128
#define KIN 128
#define NOUT (HEADS * CH)          // 512
#define NH (NNODES * HEADS)        // 200000
#define ETOT (NEDGES + NNODES)     // 450000
#define NEG_SLOPE 0.2f
#define MTILES ((NNODES + 127) / 128)   // 391

// -------- scratch --------
__device__ float g_h[(size_t)NNODES * NOUT];
__device__ float g_asrc[NH];
__device__ float g_adst[NH];
__device__ float g_rden[NH];
__device__ float g_eexp[(size_t)ETOT * HEADS];
__device__ int   g_deg[NNODES];
__device__ int   g_start[NNODES];
__device__ int   g_work[NNODES];
__device__ int   g_csr[ETOT];
__device__ int   g_total;

__device__ __forceinline__ float lrelu(float v) { return v > 0.f ? v : NEG_SLOPE * v; }

// ------------------------------------------------------------------
__global__ void zero_kernel() {
    int i = blockIdx.x * blockDim.x + threadIdx.x;
    if (i < NNODES) g_deg[i] = 0;
    if (i == 0) g_total = 0;
}

// ==================================================================
// TF32 GEMM via mma.sync (m16n8k8), 128x128 tile, fused score epilogue
// ==================================================================
#define SA_STR 36    // floats; frag bank = 4m+k (unique); fill = float4, 16B-aligned (144B rows)
#define SB_STR 136   // floats; frag bank = 8k+n (unique); fill = scalar, conflict-free

__device__ __forceinline__ uint32_t f2tf32(float x) {  // RNE round to tf32
    uint32_t u = __float_as_uint(x);
    uint32_t r = u + 0xFFFu + ((u >> 13) & 1u);
    return r & 0xFFFFE000u;
}

__device__ __forceinline__ void mma_tf32(float* c, const uint32_t* a, const uint32_t* b) {
    asm volatile(
        "mma.sync.aligned.m16n8k8.row.col.f32.tf32.tf32.f32 "
        "{%0,%1,%2,%3}, {%4,%5,%6,%7}, {%8,%9}, {%0,%1,%2,%3};"
        : "+f"(c[0]), "+f"(c[1]), "+f"(c[2]), "+f"(c[3])
        : "r"(a[0]), "r"(a[1]), "r"(a[2]), "r"(a[3]), "r"(b[0]), "r"(b[1]));
}

__global__ __launch_bounds__(256) void gemm_mma_kernel(const float* __restrict__ X,
                                                       const float* __restrict__ W,
                                                       const float* __restrict__ att_src,
                                                       const float* __restrict__ att_dst) {
    __shared__ uint32_t sA[128 * SA_STR];   // [m][k] tf32
    __shared__ uint32_t sB[32 * SB_STR];    // [k][n] tf32
    __shared__ float s_att[256];            // [0:128) att_src, [128:256) att_dst
    __shared__ float s_sc[128 * 2];         // per-row (s, d) accumulators

    const int tid = threadIdx.x;
    const int lane = tid & 31;
    const int wid = tid >> 5;
    const int groupID = lane >> 2;
    const int tid4 = lane & 3;
    const int warp_m = wid >> 2;    // 0..1
    const int warp_n = wid & 3;     // 0..3
    const int bm = blockIdx.x * 128;
    const int head = blockIdx.y;

    if (tid < 128) s_att[tid] = att_src[head * CH + tid];
    else s_att[tid] = att_dst[head * CH + (tid - 128)];
    if (tid < 256) { s_sc[tid] = 0.f; }  // 256 entries

    float c[4][4][4];
#pragma unroll
    for (int mt = 0; mt < 4; mt++)
#pragma unroll
        for (int nt = 0; nt < 4; nt++)
#pragma unroll
            for (int r = 0; r < 4; r++) c[mt][nt][r] = 0.f;

#pragma unroll 1
    for (int kc = 0; kc < 4; kc++) {
        if (kc) __syncthreads();  // protect smem reuse
        // fill A: 128 rows x 32 k; thread -> (m = idx/8, q = idx%8), float4
#pragma unroll
        for (int it = 0; it < 4; it++) {
            const int idx = it * 256 + tid;
            const int m = idx >> 3;
            const int q = idx & 7;
            const int r = bm + m;
            float4 v = (r < NNODES) ? *(const float4*)&X[(size_t)r * KIN + kc * 32 + q * 4]
                                    : make_float4(0.f, 0.f, 0.f, 0.f);
            uint4 t;
            t.x = f2tf32(v.x); t.y = f2tf32(v.y); t.z = f2tf32(v.z); t.w = f2tf32(v.w);
            *(uint4*)&sA[m * SA_STR + q * 4] = t;
        }
        // fill B: 32 k x 128 n
#pragma unroll
        for (int it = 0; it < 16; it++) {
            const int idx = it * 256 + tid;
            const int k = idx >> 7;
            const int n = idx & 127;
            sB[k * SB_STR + n] = f2tf32(W[(size_t)(kc * 32 + k) * NOUT + head * 128 + n]);
        }
        __syncthreads();

#pragma unroll
        for (int ks = 0; ks < 4; ks++) {
            const int kb = ks * 8;
            uint32_t a[4][4];
#pragma unroll
            for (int mt = 0; mt < 4; mt++) {
                const int m0 = warp_m * 64 + mt * 16 + groupID;
                a[mt][0] = sA[m0 * SA_STR + kb + tid4];
                a[mt][1] = sA[(m0 + 8) * SA_STR + kb + tid4];
                a[mt][2] = sA[m0 * SA_STR + kb + tid4 + 4];
                a[mt][3] = sA[(m0 + 8) * SA_STR + kb + tid4 + 4];
            }
            uint32_t b[4][2];
#pragma unroll
            for (int nt = 0; nt < 4; nt++) {
                const int n0 = warp_n * 32 + nt * 8 + groupID;
                b[nt][0] = sB[(kb + tid4) * SB_STR + n0];
                b[nt][1] = sB[(kb + tid4 + 4) * SB_STR + n0];
            }
#pragma unroll
            for (int mt = 0; mt < 4; mt++)
#pragma unroll
                for (int nt = 0; nt < 4; nt++) mma_tf32(c[mt][nt], a[mt], b[nt]);
        }
    }
    __syncthreads();

    // ---- epilogue: store h + fused attention scores ----
#pragma unroll
    for (int mt = 0; mt < 4; mt++) {
        const int mloc0 = warp_m * 64 + mt * 16 + groupID;  // local row (c0/c1)
        const int mloc1 = mloc0 + 8;                        // local row (c2/c3)
        float s0 = 0.f, d0 = 0.f, s1 = 0.f, d1 = 0.f;
#pragma unroll
        for (int nt = 0; nt < 4; nt++) {
            const int col = warp_n * 32 + nt * 8 + 2 * tid4;
            const float sa0 = s_att[col], sa1 = s_att[col + 1];
            const float da0 = s_att[128 + col], da1 = s_att[128 + col + 1];
            s0 = fmaf(c[mt][nt][0], sa0, fmaf(c[mt][nt][1], sa1, s0));
            d0 = fmaf(c[mt][nt][0], da0, fmaf(c[mt][nt][1], da1, d0));
            s1 = fmaf(c[mt][nt][2], sa0, fmaf(c[mt][nt][3], sa1, s1));
            d1 = fmaf(c[mt][nt][2], da0, fmaf(c[mt][nt][3], da1, d1));
        }
#pragma unroll
        for (int o = 1; o <= 2; o <<= 1) {
            s0 += __shfl_xor_sync(0xffffffffu, s0, o);
            d0 += __shfl_xor_sync(0xffffffffu, d0, o);
            s1 += __shfl_xor_sync(0xffffffffu, s1, o);
            d1 += __shfl_xor_sync(0xffffffffu, d1, o);
        }
        if (tid4 == 0) {
            atomicAdd(&s_sc[mloc0 * 2 + 0], s0);
            atomicAdd(&s_sc[mloc0 * 2 + 1], d0);
            atomicAdd(&s_sc[mloc1 * 2 + 0], s1);
            atomicAdd(&s_sc[mloc1 * 2 + 1], d1);
        }
        const int r0 = bm + mloc0;
        const int r1 = bm + mloc1;
#pragma unroll
        for (int nt = 0; nt < 4; nt++) {
            const int col = head * 128 + warp_n * 32 + nt * 8 + 2 * tid4;
            if (r0 < NNODES)
                *(float2*)&g_h[(size_t)r0 * NOUT + col] = make_float2(c[mt][nt][0], c[mt][nt][1]);
            if (r1 < NNODES)
                *(float2*)&g_h[(size_t)r1 * NOUT + col] = make_float2(c[mt][nt][2], c[mt][nt][3]);
        }
    }
    __syncthreads();
    if (tid < 128) {
        const int r = bm + tid;
        if (r < NNODES) {
            g_asrc[r * 4 + head] = s_sc[tid * 2 + 0];
            g_adst[r * 4 + head] = s_sc[tid * 2 + 1];
        }
    }
}

// ------------------------------------------------------------------
// CSR build
// ------------------------------------------------------------------
__global__ __launch_bounds__(256) void hist_kernel(const int* __restrict__ ei) {
    const int e = blockIdx.x * blockDim.x + threadIdx.x;
    if (e >= ETOT) return;
    const int dst = (e < NEDGES) ? ei[NEDGES + e] : (e - NEDGES);
    atomicAdd(&g_deg[dst], 1);
}

__global__ __launch_bounds__(256) void scan_kernel() {
    __shared__ int wsum[8];
    __shared__ int s_base;
    const int tid = threadIdx.x;
    const int lane = tid & 31;
    const int warp = tid >> 5;
    const int i = blockIdx.x * 256 + tid;

    const int d = (i < NNODES) ? g_deg[i] : 0;
    int v = d;
#pragma unroll
    for (int o = 1; o < 32; o <<= 1) {
        int t = __shfl_up_sync(0xffffffffu, v, o);
        if (lane >= o) v += t;
    }
    if (lane == 31) wsum[warp] = v;
    __syncthreads();
    if (tid == 0) {
        int run = 0;
#pragma unroll
        for (int w = 0; w < 8; w++) { int t = wsum[w]; wsum[w] = run; run += t; }
        s_base = atomicAdd(&g_total, run);
    }
    __syncthreads();
    if (i < NNODES) {
        const int excl = s_base + wsum[warp] + v - d;
        g_start[i] = excl;
        g_work[i] = excl;
    }
}

__global__ __launch_bounds__(256) void scatter_kernel(const int* __restrict__ ei) {
    const int e = blockIdx.x * blockDim.x + threadIdx.x;
    if (e >= ETOT) return;
    int src, dst;
    if (e < NEDGES) { src = ei[e]; dst = ei[NEDGES + e]; }
    else { src = dst = e - NEDGES; }
    const int pos = atomicAdd(&g_work[dst], 1);
    g_csr[pos] = src;
}

// ------------------------------------------------------------------
// softmax: one warp per dst node (all 4 heads)
// ------------------------------------------------------------------
__global__ __launch_bounds__(256) void softmax_kernel() {
    const int gw = blockIdx.x * 8 + (threadIdx.x >> 5);
    const int lane = threadIdx.x & 31;
    if (gw >= NNODES) return;

    const int start = g_start[gw];
    const int deg = g_deg[gw];
    const float4 ad = *(const float4*)&g_adst[gw * 4];

    float4 mx = make_float4(-INFINITY, -INFINITY, -INFINITY, -INFINITY);
    for (int i = lane; i < deg; i += 32) {
        const int src = g_csr[start + i];
        const float4 as = *(const float4*)&g_asrc[src * 4];
        mx.x = fmaxf(mx.x, lrelu(as.x + ad.x));
        mx.y = fmaxf(mx.y, lrelu(as.y + ad.y));
        mx.z = fmaxf(mx.z, lrelu(as.z + ad.z));
        mx.w = fmaxf(mx.w, lrelu(as.w + ad.w));
    }
#pragma unroll
    for (int o = 16; o; o >>= 1) {
        mx.x = fmaxf(mx.x, __shfl_xor_sync(0xffffffffu, mx.x, o));
        mx.y = fmaxf(mx.y, __shfl_xor_sync(0xffffffffu, mx.y, o));
        mx.z = fmaxf(mx.z, __shfl_xor_sync(0xffffffffu, mx.z, o));
        mx.w = fmaxf(mx.w, __shfl_xor_sync(0xffffffffu, mx.w, o));
    }

    float4 sm = make_float4(0.f, 0.f, 0.f, 0.f);
    for (int i = lane; i < deg; i += 32) {
        const int src = g_csr[start + i];
        const float4 as = *(const float4*)&g_asrc[src * 4];
        float4 e;
        e.x = __expf(lrelu(as.x + ad.x) - mx.x);
        e.y = __expf(lrelu(as.y + ad.y) - mx.y);
        e.z = __expf(lrelu(as.z + ad.z) - mx.z);
        e.w = __expf(lrelu(as.w + ad.w) - mx.w);
        *(float4*)&g_eexp[(size_t)(start + i) * 4] = e;
        sm.x += e.x; sm.y += e.y; sm.z += e.z; sm.w += e.w;
    }
#pragma unroll
    for (int o = 16; o; o >>= 1) {
        sm.x += __shfl_xor_sync(0xffffffffu, sm.x, o);
        sm.y += __shfl_xor_sync(0xffffffffu, sm.y, o);
        sm.z += __shfl_xor_sync(0xffffffffu, sm.z, o);
        sm.w += __shfl_xor_sync(0xffffffffu, sm.w, o);
    }
    if (lane == 0) {
        float4 r;
        r.x = 1.0f / sm.x; r.y = 1.0f / sm.y; r.z = 1.0f / sm.z; r.w = 1.0f / sm.w;
        *(float4*)&g_rden[gw * 4] = r;
    }
}

// ------------------------------------------------------------------
// aggregation: one warp per (dst, head)
// ------------------------------------------------------------------
__global__ __launch_bounds__(256) void aggregate_kernel(const float* __restrict__ bias,
                                                        float* __restrict__ out) {
    const int gw = blockIdx.x * 8 + (threadIdx.x >> 5);
    const int lane = threadIdx.x & 31;
    if (gw >= NH) return;
    const int dst = gw >> 2;
    const int hd = gw & 3;

    const int start = g_start[dst];
    const int deg = g_deg[dst];
    const float invd = g_rden[dst * 4 + hd];

    float4 acc = make_float4(0.f, 0.f, 0.f, 0.f);
    for (int base = 0; base < deg; base += 32) {
        const int n = min(32, deg - base);
        int src_l = 0;
        float e_l = 0.f;
        if (lane < n) {
            src_l = g_csr[start + base + lane];
            e_l = g_eexp[(size_t)(start + base + lane) * 4 + hd];
        }
        for (int j = 0; j < n; j++) {
            const int src = __shfl_sync(0xffffffffu, src_l, j);
            const float al = __shfl_sync(0xffffffffu, e_l, j) * invd;
            const float4 hv = *(const float4*)&g_h[(size_t)src * NOUT + hd * CH + lane * 4];
            acc.x = fmaf(al, hv.x, acc.x);
            acc.y = fmaf(al, hv.y, acc.y);
            acc.z = fmaf(al, hv.z, acc.z);
            acc.w = fmaf(al, hv.w, acc.w);
        }
    }
    const float4 b = *(const float4*)&bias[hd * CH + lane * 4];
    acc.x += b.x; acc.y += b.y; acc.z += b.z; acc.w += b.w;
    *(float4*)&out[(size_t)dst * NOUT + hd * CH + lane * 4] = acc;
}

// ------------------------------------------------------------------
extern "C" void kernel_launch(void* const* d_in, const int* in_sizes, int n_in,
                              void* d_out, int out_size) {
    const float* x       = (const float*)d_in[0];
    const int* ei        = (const int*)d_in[1];
    const float* W       = (const float*)d_in[2];
    const float* att_src = (const float*)d_in[3];
    const float* att_dst = (const float*)d_in[4];
    const float* bias    = (const float*)d_in[5];
    float* out           = (float*)d_out;

    (void)in_sizes; (void)n_in; (void)out_size;

    zero_kernel<<<(NNODES + 255) / 256, 256>>>();
    {
        dim3 grid(MTILES, HEADS);
        gemm_mma_kernel<<<grid, 256>>>(x, W, att_src, att_dst);
    }
    hist_kernel<<<(ETOT + 255) / 256, 256>>>(ei);
    scan_kernel<<<(NNODES + 255) / 256, 256>>>();
    scatter_kernel<<<(ETOT + 255) / 256, 256>>>(ei);
    softmax_kernel<<<(NNODES + 7) / 8, 256>>>();
    aggregate_kernel<<<(NH + 7) / 8, 256>>>(bias, out);
}

// round 9
// speedup vs baseline: 2.7047x; 1.0395x over previous
#include <cuda_runtime.h>
#include <math.h>
#include <stdint.h>

#define NNODES 50000
#define NEDGES 400000
#define HEADS 4
#define CH 128
#define KIN 128
#define NOUT (HEADS * CH)          // 512
#define NH (NNODES * HEADS)        // 200000
#define ETOT (NEDGES + NNODES)     // 450000
#define NEG_SLOPE 0.2f
#define MTILES ((NNODES + 127) / 128)   // 391

// -------- scratch --------
__device__ float g_h[(size_t)NNODES * NOUT];
__device__ float g_xr[(size_t)NNODES * KIN];   // tf32-rounded X
__device__ float g_wr[(size_t)KIN * NOUT];     // tf32-rounded W
__device__ float g_asrc[NH];
__device__ float g_adst[NH];
__device__ float g_rden[NH];
__device__ float g_eexp[(size_t)ETOT * HEADS];
__device__ int   g_deg[NNODES];
__device__ int   g_start[NNODES];
__device__ int   g_work[NNODES];
__device__ int   g_csr[ETOT];
__device__ int   g_total;

__device__ __forceinline__ float lrelu(float v) { return v > 0.f ? v : NEG_SLOPE * v; }

__device__ __forceinline__ uint32_t f2tf32(float x) {  // RNE round to tf32
    uint32_t u = __float_as_uint(x);
    uint32_t r = u + 0xFFFu + ((u >> 13) & 1u);
    return r & 0xFFFFE000u;
}

// ------------------------------------------------------------------
// prep: RNE-round X and W to tf32 patterns; zero deg counters
// ------------------------------------------------------------------
#define NX4 (NNODES * KIN / 4)     // 1,600,000
#define NW4 (KIN * NOUT / 4)       // 16,384
__global__ __launch_bounds__(256) void prep_kernel(const float* __restrict__ X,
                                                   const float* __restrict__ W) {
    const int idx = blockIdx.x * blockDim.x + threadIdx.x;
    if (idx < NX4) {
        const float4 v = *(const float4*)&X[idx * 4];
        uint4 t;
        t.x = f2tf32(v.x); t.y = f2tf32(v.y); t.z = f2tf32(v.z); t.w = f2tf32(v.w);
        *(uint4*)&g_xr[idx * 4] = t;
    } else if (idx < NX4 + NW4) {
        const int j = idx - NX4;
        const float4 v = *(const float4*)&W[j * 4];
        uint4 t;
        t.x = f2tf32(v.x); t.y = f2tf32(v.y); t.z = f2tf32(v.z); t.w = f2tf32(v.w);
        *(uint4*)&g_wr[j * 4] = t;
    }
    if (idx < NNODES) g_deg[idx] = 0;
    if (idx == 0) g_total = 0;
}

// ==================================================================
// TF32 GEMM via mma.sync (m16n8k8), 128x128 tile, cp.async double
// buffer over 4 K-chunks of 32, fused score epilogue.
// ==================================================================
#define SA_STR 36     // floats/row; frag bank = 4m+k unique
#define SB_STR 136    // floats/row; frag bank = 8k+n unique
#define SA_CH (128 * SA_STR)   // 4608 floats / chunk buffer
#define SB_CH (32 * SB_STR)    // 4352
#define SMEM_DYN ((2 * SA_CH + 2 * SB_CH) * 4)   // 71680 bytes

__device__ __forceinline__ void mma_tf32(float* c, const uint32_t* a, const uint32_t* b) {
    asm volatile(
        "mma.sync.aligned.m16n8k8.row.col.f32.tf32.tf32.f32 "
        "{%0,%1,%2,%3}, {%4,%5,%6,%7}, {%8,%9}, {%0,%1,%2,%3};"
        : "+f"(c[0]), "+f"(c[1]), "+f"(c[2]), "+f"(c[3])
        : "r"(a[0]), "r"(a[1]), "r"(a[2]), "r"(a[3]), "r"(b[0]), "r"(b[1]));
}

__device__ __forceinline__ void cp16(uint32_t saddr, const void* gptr, uint32_t sz) {
    asm volatile("cp.async.cg.shared.global [%0], [%1], 16, %2;"
                 :: "r"(saddr), "l"(gptr), "r"(sz) : "memory");
}

__global__ __launch_bounds__(256, 2) void gemm_mma_kernel(const float* __restrict__ att_src,
                                                          const float* __restrict__ att_dst) {
    extern __shared__ float dyn[];
    float* sAf = dyn;                 // [2][SA_CH]
    float* sBf = dyn + 2 * SA_CH;     // [2][SB_CH]
    __shared__ float s_att[256];
    __shared__ float s_sc[256];

    const int tid = threadIdx.x;
    const int lane = tid & 31;
    const int wid = tid >> 5;
    const int groupID = lane >> 2;
    const int tid4 = lane & 3;
    const int warp_m = wid >> 2;    // 0..1
    const int warp_n = wid & 3;     // 0..3
    const int bm = blockIdx.x * 128;
    const int head = blockIdx.y;

    if (tid < 128) s_att[tid] = att_src[head * CH + tid];
    else s_att[tid] = att_dst[head * CH + (tid - 128)];
    s_sc[tid] = 0.f;

    // per-thread cp.async coordinates
    const int a_row = tid >> 1;               // with 4 iters: rows tid>>1 + it*... recompute below
    (void)a_row;

    const uint32_t sA_base = (uint32_t)__cvta_generic_to_shared(sAf);
    const uint32_t sB_base = (uint32_t)__cvta_generic_to_shared(sBf);

    // load chunk kc into buffer b
    auto load_chunk = [&](int kc, int b) {
#pragma unroll
        for (int it = 0; it < 4; it++) {
            const int idx = it * 256 + tid;
            const int row = idx >> 3;          // 0..127
            const int seg = idx & 7;           // 0..7 (x4 floats)
            const uint32_t sz = (bm + row < NNODES) ? 16u : 0u;
            cp16(sA_base + (b * SA_CH + row * SA_STR + seg * 4) * 4,
                 &g_xr[(size_t)(bm + row) * KIN + kc * 32 + seg * 4], sz);
        }
#pragma unroll
        for (int it = 0; it < 4; it++) {
            const int idx = it * 256 + tid;
            const int k = idx >> 5;            // 0..31
            const int seg = idx & 31;          // 0..31 (x4 floats)
            cp16(sB_base + (b * SB_CH + k * SB_STR + seg * 4) * 4,
                 &g_wr[(size_t)(kc * 32 + k) * NOUT + head * 128 + seg * 4], 16u);
        }
    };

    float c[4][4][4];
#pragma unroll
    for (int mt = 0; mt < 4; mt++)
#pragma unroll
        for (int nt = 0; nt < 4; nt++)
#pragma unroll
            for (int r = 0; r < 4; r++) c[mt][nt][r] = 0.f;

    load_chunk(0, 0);
    asm volatile("cp.async.commit_group;" ::: "memory");

#pragma unroll 1
    for (int kc = 0; kc < 4; kc++) {
        const int cur = kc & 1;
        if (kc < 3) {
            load_chunk(kc + 1, cur ^ 1);
            asm volatile("cp.async.commit_group;" ::: "memory");
            asm volatile("cp.async.wait_group 1;" ::: "memory");
        } else {
            asm volatile("cp.async.wait_group 0;" ::: "memory");
        }
        __syncthreads();

        const uint32_t* sA = (const uint32_t*)(sAf + cur * SA_CH);
        const uint32_t* sB = (const uint32_t*)(sBf + cur * SB_CH);
#pragma unroll
        for (int ks = 0; ks < 4; ks++) {
            const int kb = ks * 8;
            uint32_t a[4][4];
#pragma unroll
            for (int mt = 0; mt < 4; mt++) {
                const int m0 = warp_m * 64 + mt * 16 + groupID;
                a[mt][0] = sA[m0 * SA_STR + kb + tid4];
                a[mt][1] = sA[(m0 + 8) * SA_STR + kb + tid4];
                a[mt][2] = sA[m0 * SA_STR + kb + tid4 + 4];
                a[mt][3] = sA[(m0 + 8) * SA_STR + kb + tid4 + 4];
            }
            uint32_t b[4][2];
#pragma unroll
            for (int nt = 0; nt < 4; nt++) {
                const int n0 = warp_n * 32 + nt * 8 + groupID;
                b[nt][0] = sB[(kb + tid4) * SB_STR + n0];
                b[nt][1] = sB[(kb + tid4 + 4) * SB_STR + n0];
            }
#pragma unroll
            for (int mt = 0; mt < 4; mt++)
#pragma unroll
                for (int nt = 0; nt < 4; nt++) mma_tf32(c[mt][nt], a[mt], b[nt]);
        }
        __syncthreads();
    }

    // ---- epilogue: store h + fused attention scores ----
#pragma unroll
    for (int mt = 0; mt < 4; mt++) {
        const int mloc0 = warp_m * 64 + mt * 16 + groupID;
        const int mloc1 = mloc0 + 8;
        float s0 = 0.f, d0 = 0.f, s1 = 0.f, d1 = 0.f;
#pragma unroll
        for (int nt = 0; nt < 4; nt++) {
            const int col = warp_n * 32 + nt * 8 + 2 * tid4;
            const float sa0 = s_att[col], sa1 = s_att[col + 1];
            const float da0 = s_att[128 + col], da1 = s_att[128 + col + 1];
            s0 = fmaf(c[mt][nt][0], sa0, fmaf(c[mt][nt][1], sa1, s0));
            d0 = fmaf(c[mt][nt][0], da0, fmaf(c[mt][nt][1], da1, d0));
            s1 = fmaf(c[mt][nt][2], sa0, fmaf(c[mt][nt][3], sa1, s1));
            d1 = fmaf(c[mt][nt][2], da0, fmaf(c[mt][nt][3], da1, d1));
        }
#pragma unroll
        for (int o = 1; o <= 2; o <<= 1) {
            s0 += __shfl_xor_sync(0xffffffffu, s0, o);
            d0 += __shfl_xor_sync(0xffffffffu, d0, o);
            s1 += __shfl_xor_sync(0xffffffffu, s1, o);
            d1 += __shfl_xor_sync(0xffffffffu, d1, o);
        }
        if (tid4 == 0) {
            atomicAdd(&s_sc[mloc0 * 2 + 0], s0);
            atomicAdd(&s_sc[mloc0 * 2 + 1], d0);
            atomicAdd(&s_sc[mloc1 * 2 + 0], s1);
            atomicAdd(&s_sc[mloc1 * 2 + 1], d1);
        }
        const int r0 = bm + mloc0;
        const int r1 = bm + mloc1;
#pragma unroll
        for (int nt = 0; nt < 4; nt++) {
            const int col = head * 128 + warp_n * 32 + nt * 8 + 2 * tid4;
            if (r0 < NNODES)
                *(float2*)&g_h[(size_t)r0 * NOUT + col] = make_float2(c[mt][nt][0], c[mt][nt][1]);
            if (r1 < NNODES)
                *(float2*)&g_h[(size_t)r1 * NOUT + col] = make_float2(c[mt][nt][2], c[mt][nt][3]);
        }
    }
    __syncthreads();
    if (tid < 128) {
        const int r = bm + tid;
        if (r < NNODES) {
            g_asrc[r * 4 + head] = s_sc[tid * 2 + 0];
            g_adst[r * 4 + head] = s_sc[tid * 2 + 1];
        }
    }
}

// ------------------------------------------------------------------
// CSR build
// ------------------------------------------------------------------
__global__ __launch_bounds__(256) void hist_kernel(const int* __restrict__ ei) {
    const int e = blockIdx.x * blockDim.x + threadIdx.x;
    if (e >= ETOT) return;
    const int dst = (e < NEDGES) ? ei[NEDGES + e] : (e - NEDGES);
    atomicAdd(&g_deg[dst], 1);
}

__global__ __launch_bounds__(256) void scan_kernel() {
    __shared__ int wsum[8];
    __shared__ int s_base;
    const int tid = threadIdx.x;
    const int lane = tid & 31;
    const int warp = tid >> 5;
    const int i = blockIdx.x * 256 + tid;

    const int d = (i < NNODES) ? g_deg[i] : 0;
    int v = d;
#pragma unroll
    for (int o = 1; o < 32; o <<= 1) {
        int t = __shfl_up_sync(0xffffffffu, v, o);
        if (lane >= o) v += t;
    }
    if (lane == 31) wsum[warp] = v;
    __syncthreads();
    if (tid == 0) {
        int run = 0;
#pragma unroll
        for (int w = 0; w < 8; w++) { int t = wsum[w]; wsum[w] = run; run += t; }
        s_base = atomicAdd(&g_total, run);
    }
    __syncthreads();
    if (i < NNODES) {
        const int excl = s_base + wsum[warp] + v - d;
        g_start[i] = excl;
        g_work[i] = excl;
    }
}

__global__ __launch_bounds__(256) void scatter_kernel(const int* __restrict__ ei) {
    const int e = blockIdx.x * blockDim.x + threadIdx.x;
    if (e >= ETOT) return;
    int src, dst;
    if (e < NEDGES) { src = ei[e]; dst = ei[NEDGES + e]; }
    else { src = dst = e - NEDGES; }
    const int pos = atomicAdd(&g_work[dst], 1);
    g_csr[pos] = src;
}

// ------------------------------------------------------------------
// softmax: one warp per dst node (all 4 heads)
// ------------------------------------------------------------------
__global__ __launch_bounds__(256) void softmax_kernel() {
    const int gw = blockIdx.x * 8 + (threadIdx.x >> 5);
    const int lane = threadIdx.x & 31;
    if (gw >= NNODES) return;

    const int start = g_start[gw];
    const int deg = g_deg[gw];
    const float4 ad = *(const float4*)&g_adst[gw * 4];

    float4 mx = make_float4(-INFINITY, -INFINITY, -INFINITY, -INFINITY);
    for (int i = lane; i < deg; i += 32) {
        const int src = g_csr[start + i];
        const float4 as = *(const float4*)&g_asrc[src * 4];
        mx.x = fmaxf(mx.x, lrelu(as.x + ad.x));
        mx.y = fmaxf(mx.y, lrelu(as.y + ad.y));
        mx.z = fmaxf(mx.z, lrelu(as.z + ad.z));
        mx.w = fmaxf(mx.w, lrelu(as.w + ad.w));
    }
#pragma unroll
    for (int o = 16; o; o >>= 1) {
        mx.x = fmaxf(mx.x, __shfl_xor_sync(0xffffffffu, mx.x, o));
        mx.y = fmaxf(mx.y, __shfl_xor_sync(0xffffffffu, mx.y, o));
        mx.z = fmaxf(mx.z, __shfl_xor_sync(0xffffffffu, mx.z, o));
        mx.w = fmaxf(mx.w, __shfl_xor_sync(0xffffffffu, mx.w, o));
    }

    float4 sm = make_float4(0.f, 0.f, 0.f, 0.f);
    for (int i = lane; i < deg; i += 32) {
        const int src = g_csr[start + i];
        const float4 as = *(const float4*)&g_asrc[src * 4];
        float4 e;
        e.x = __expf(lrelu(as.x + ad.x) - mx.x);
        e.y = __expf(lrelu(as.y + ad.y) - mx.y);
        e.z = __expf(lrelu(as.z + ad.z) - mx.z);
        e.w = __expf(lrelu(as.w + ad.w) - mx.w);
        *(float4*)&g_eexp[(size_t)(start + i) * 4] = e;
        sm.x += e.x; sm.y += e.y; sm.z += e.z; sm.w += e.w;
    }
#pragma unroll
    for (int o = 16; o; o >>= 1) {
        sm.x += __shfl_xor_sync(0xffffffffu, sm.x, o);
        sm.y += __shfl_xor_sync(0xffffffffu, sm.y, o);
        sm.z += __shfl_xor_sync(0xffffffffu, sm.z, o);
        sm.w += __shfl_xor_sync(0xffffffffu, sm.w, o);
    }
    if (lane == 0) {
        float4 r;
        r.x = 1.0f / sm.x; r.y = 1.0f / sm.y; r.z = 1.0f / sm.z; r.w = 1.0f / sm.w;
        *(float4*)&g_rden[gw * 4] = r;
    }
}

// ------------------------------------------------------------------
// aggregation: one warp per (dst, head)
// ------------------------------------------------------------------
__global__ __launch_bounds__(256) void aggregate_kernel(const float* __restrict__ bias,
                                                        float* __restrict__ out) {
    const int gw = blockIdx.x * 8 + (threadIdx.x >> 5);
    const int lane = threadIdx.x & 31;
    if (gw >= NH) return;
    const int dst = gw >> 2;
    const int hd = gw & 3;

    const int start = g_start[dst];
    const int deg = g_deg[dst];
    const float invd = g_rden[dst * 4 + hd];

    float4 acc = make_float4(0.f, 0.f, 0.f, 0.f);
    for (int base = 0; base < deg; base += 32) {
        const int n = min(32, deg - base);
        int src_l = 0;
        float e_l = 0.f;
        if (lane < n) {
            src_l = g_csr[start + base + lane];
            e_l = g_eexp[(size_t)(start + base + lane) * 4 + hd];
        }
        for (int j = 0; j < n; j++) {
            const int src = __shfl_sync(0xffffffffu, src_l, j);
            const float al = __shfl_sync(0xffffffffu, e_l, j) * invd;
            const float4 hv = *(const float4*)&g_h[(size_t)src * NOUT + hd * CH + lane * 4];
            acc.x = fmaf(al, hv.x, acc.x);
            acc.y = fmaf(al, hv.y, acc.y);
            acc.z = fmaf(al, hv.z, acc.z);
            acc.w = fmaf(al, hv.w, acc.w);
        }
    }
    const float4 b = *(const float4*)&bias[hd * CH + lane * 4];
    acc.x += b.x; acc.y += b.y; acc.z += b.z; acc.w += b.w;
    *(float4*)&out[(size_t)dst * NOUT + hd * CH + lane * 4] = acc;
}

// ------------------------------------------------------------------
extern "C" void kernel_launch(void* const* d_in, const int* in_sizes, int n_in,
                              void* d_out, int out_size) {
    const float* x       = (const float*)d_in[0];
    const int* ei        = (const int*)d_in[1];
    const float* W       = (const float*)d_in[2];
    const float* att_src = (const float*)d_in[3];
    const float* att_dst = (const float*)d_in[4];
    const float* bias    = (const float*)d_in[5];
    float* out           = (float*)d_out;

    (void)in_sizes; (void)n_in; (void)out_size;

    cudaFuncSetAttribute(gemm_mma_kernel, cudaFuncAttributeMaxDynamicSharedMemorySize, SMEM_DYN);

    prep_kernel<<<(NX4 + NW4 + 255) / 256, 256>>>(x, W);
    {
        dim3 grid(MTILES, HEADS);
        gemm_mma_kernel<<<grid, 256, SMEM_DYN>>>(att_src, att_dst);
    }
    hist_kernel<<<(ETOT + 255) / 256, 256>>>(ei);
    scan_kernel<<<(NNODES + 255) / 256, 256>>>();
    scatter_kernel<<<(ETOT + 255) / 256, 256>>>(ei);
    softmax_kernel<<<(NNODES + 7) / 8, 256>>>();
    aggregate_kernel<<<(NH + 7) / 8, 256>>>(bias, out);
}

// round 11
// speedup vs baseline: 2.7088x; 1.0015x over previous
#include <cuda_runtime.h>
#include <math.h>
#include <stdint.h>

#define NNODES 50000
#define NEDGES 400000
#define HEADS 4
#define CH 128
#define KIN 128
#define NOUT (HEADS * CH)          // 512
#define NH (NNODES * HEADS)        // 200000
#define ETOT (NEDGES + NNODES)     // 450000
#define NEG_SLOPE 0.2f
#define MTILES ((NNODES + 127) / 128)   // 391

// -------- scratch --------
__device__ float g_h[(size_t)NNODES * NOUT];
__device__ float g_xp[(size_t)NNODES * KIN];   // tf32-rounded, k-permuted X
__device__ float g_wtp[(size_t)NOUT * KIN];    // tf32-rounded, transposed, k-permuted W
__device__ float g_asrc[NH];
__device__ float g_adst[NH];
__device__ float g_rden[NH];
__device__ float g_eexp[(size_t)ETOT * HEADS];
__device__ int   g_deg[NNODES];
__device__ int   g_start[NNODES];
__device__ int   g_work[NNODES];
__device__ int   g_csr[ETOT];
__device__ int   g_total;

__device__ __forceinline__ float lrelu(float v) { return v > 0.f ? v : NEG_SLOPE * v; }

__device__ __forceinline__ uint32_t f2tf32(float x) {  // RNE round to tf32
    uint32_t u = __float_as_uint(x);
    uint32_t r = u + 0xFFFu + ((u >> 13) & 1u);
    return r & 0xFFFFE000u;
}

// ------------------------------------------------------------------
// prep: round to tf32 + permute k within 8-groups (pos = 2*(k&3) + (k>>2))
//   X  -> g_xp   (same row layout, permuted k)
//   W  -> g_wtp  ([n_global][k_perm], transposed)
// Also zeros deg counters.
// ------------------------------------------------------------------
#define NXG (NNODES * KIN / 8)     // 800,000 X groups
#define NWG (NOUT * KIN / 8)       // 8,192 W groups
__global__ __launch_bounds__(256) void prep_kernel(const float* __restrict__ X,
                                                   const float* __restrict__ W) {
    const int idx = blockIdx.x * blockDim.x + threadIdx.x;
    if (idx < NXG) {
        const size_t base = (size_t)idx * 8;
        const float4 lo = *(const float4*)&X[base];
        const float4 hi = *(const float4*)&X[base + 4];
        // out[0..3] = {v0,v4,v1,v5}, out[4..7] = {v2,v6,v3,v7}
        uint4 o0, o1;
        o0.x = f2tf32(lo.x); o0.y = f2tf32(hi.x); o0.z = f2tf32(lo.y); o0.w = f2tf32(hi.y);
        o1.x = f2tf32(lo.z); o1.y = f2tf32(hi.z); o1.z = f2tf32(lo.w); o1.w = f2tf32(hi.w);
        *(uint4*)&g_xp[base] = o0;
        *(uint4*)&g_xp[base + 4] = o1;
    } else if (idx < NXG + NWG) {
        const int w = idx - NXG;
        const int n_glob = w >> 4;          // 0..511
        const int grp = w & 15;             // k-group
        float v[8];
#pragma unroll
        for (int j = 0; j < 8; j++) v[j] = W[(size_t)(grp * 8 + j) * NOUT + n_glob];
        float* op = &g_wtp[(size_t)n_glob * KIN + grp * 8];
        uint4 o0, o1;
        o0.x = f2tf32(v[0]); o0.y = f2tf32(v[4]); o0.z = f2tf32(v[1]); o0.w = f2tf32(v[5]);
        o1.x = f2tf32(v[2]); o1.y = f2tf32(v[6]); o1.z = f2tf32(v[3]); o1.w = f2tf32(v[7]);
        *(uint4*)op = o0;
        *(uint4*)(op + 4) = o1;
    }
    if (idx < NNODES) g_deg[idx] = 0;
    if (idx == 0) g_total = 0;
}

// ==================================================================
// TF32 GEMM via mma.sync (m16n8k8), 128x128 tile, cp.async double
// buffer, LDS.64 fragment loads via k-interleaved layouts.
// ==================================================================
#define SA_STR 40                   // floats/row (even, conflict-free bank-pairs)
#define SB_STR 40
#define SA_CH (128 * SA_STR)        // 5120 floats per buffer
#define SB_CH (128 * SB_STR)        // 5120
#define SMEM_DYN ((2 * SA_CH + 2 * SB_CH) * 4)   // 81920 bytes

__device__ __forceinline__ void mma_tf32(float* c, const uint32_t* a, const uint32_t* b) {
    asm volatile(
        "mma.sync.aligned.m16n8k8.row.col.f32.tf32.tf32.f32 "
        "{%0,%1,%2,%3}, {%4,%5,%6,%7}, {%8,%9}, {%0,%1,%2,%3};"
        : "+f"(c[0]), "+f"(c[1]), "+f"(c[2]), "+f"(c[3])
        : "r"(a[0]), "r"(a[1]), "r"(a[2]), "r"(a[3]), "r"(b[0]), "r"(b[1]));
}

__device__ __forceinline__ void cp16(uint32_t saddr, const void* gptr, uint32_t sz) {
    asm volatile("cp.async.cg.shared.global [%0], [%1], 16, %2;"
                 :: "r"(saddr), "l"(gptr), "r"(sz) : "memory");
}

__global__ __launch_bounds__(256, 2) void gemm_mma_kernel(const float* __restrict__ att_src,
                                                          const float* __restrict__ att_dst) {
    extern __shared__ float dyn[];
    float* sAf = dyn;                 // [2][SA_CH]  A: [m][k_perm]
    float* sBf = dyn + 2 * SA_CH;     // [2][SB_CH]  B: [n][k_perm]
    __shared__ float s_att[256];
    __shared__ float s_sc[256];

    const int tid = threadIdx.x;
    const int lane = tid & 31;
    const int wid = tid >> 5;
    const int groupID = lane >> 2;
    const int tid4 = lane & 3;
    const int warp_m = wid >> 2;    // 0..1
    const int warp_n = wid & 3;     // 0..3
    const int bm = blockIdx.x * 128;
    const int head = blockIdx.y;

    if (tid < 128) s_att[tid] = att_src[head * CH + tid];
    else s_att[tid] = att_dst[head * CH + (tid - 128)];
    s_sc[tid] = 0.f;

    const uint32_t sA_base = (uint32_t)__cvta_generic_to_shared(sAf);
    const uint32_t sB_base = (uint32_t)__cvta_generic_to_shared(sBf);

    // load chunk kc (32 k) into buffer b; rows of 32 floats, 8x cp16 per row
    auto load_chunk = [&](int kc, int b) {
#pragma unroll
        for (int it = 0; it < 4; it++) {
            const int idx = it * 256 + tid;
            const int row = idx >> 3;          // m: 0..127
            const int seg = idx & 7;
            const uint32_t sz = (bm + row < NNODES) ? 16u : 0u;
            cp16(sA_base + (b * SA_CH + row * SA_STR + seg * 4) * 4,
                 &g_xp[(size_t)(bm + row) * KIN + kc * 32 + seg * 4], sz);
        }
#pragma unroll
        for (int it = 0; it < 4; it++) {
            const int idx = it * 256 + tid;
            const int row = idx >> 3;          // n: 0..127
            const int seg = idx & 7;
            cp16(sB_base + (b * SB_CH + row * SB_STR + seg * 4) * 4,
                 &g_wtp[(size_t)(head * 128 + row) * KIN + kc * 32 + seg * 4], 16u);
        }
    };

    float c[4][4][4];
#pragma unroll
    for (int mt = 0; mt < 4; mt++)
#pragma unroll
        for (int nt = 0; nt < 4; nt++)
#pragma unroll
            for (int r = 0; r < 4; r++) c[mt][nt][r] = 0.f;

    load_chunk(0, 0);
    asm volatile("cp.async.commit_group;" ::: "memory");

#pragma unroll 1
    for (int kc = 0; kc < 4; kc++) {
        const int cur = kc & 1;
        if (kc < 3) {
            load_chunk(kc + 1, cur ^ 1);
            asm volatile("cp.async.commit_group;" ::: "memory");
            asm volatile("cp.async.wait_group 1;" ::: "memory");
        } else {
            asm volatile("cp.async.wait_group 0;" ::: "memory");
        }
        __syncthreads();

        const float* sA = sAf + cur * SA_CH;
        const float* sB = sBf + cur * SB_CH;
#pragma unroll
        for (int ks = 0; ks < 4; ks++) {
            const int kb = ks * 8;          // permuted: (k,k+4) -> (kb+2t4, kb+2t4+1)
            const int koff = kb + 2 * tid4;
            uint32_t a[4][4];
#pragma unroll
            for (int mt = 0; mt < 4; mt++) {
                const int m0 = warp_m * 64 + mt * 16 + groupID;
                const uint2 lo = *(const uint2*)&sA[m0 * SA_STR + koff];        // a0, a2
                const uint2 hi = *(const uint2*)&sA[(m0 + 8) * SA_STR + koff];  // a1, a3
                a[mt][0] = lo.x; a[mt][1] = hi.x; a[mt][2] = lo.y; a[mt][3] = hi.y;
            }
            uint32_t b[4][2];
#pragma unroll
            for (int nt = 0; nt < 4; nt++) {
                const int n0 = warp_n * 32 + nt * 8 + groupID;
                const uint2 bv = *(const uint2*)&sB[n0 * SB_STR + koff];        // b0, b1
                b[nt][0] = bv.x; b[nt][1] = bv.y;
            }
#pragma unroll
            for (int mt = 0; mt < 4; mt++)
#pragma unroll
                for (int nt = 0; nt < 4; nt++) mma_tf32(c[mt][nt], a[mt], b[nt]);
        }
        __syncthreads();
    }

    // ---- epilogue: store h + fused attention scores ----
#pragma unroll
    for (int mt = 0; mt < 4; mt++) {
        const int mloc0 = warp_m * 64 + mt * 16 + groupID;
        const int mloc1 = mloc0 + 8;
        float s0 = 0.f, d0 = 0.f, s1 = 0.f, d1 = 0.f;
#pragma unroll
        for (int nt = 0; nt < 4; nt++) {
            const int col = warp_n * 32 + nt * 8 + 2 * tid4;
            const float sa0 = s_att[col], sa1 = s_att[col + 1];
            const float da0 = s_att[128 + col], da1 = s_att[128 + col + 1];
            s0 = fmaf(c[mt][nt][0], sa0, fmaf(c[mt][nt][1], sa1, s0));
            d0 = fmaf(c[mt][nt][0], da0, fmaf(c[mt][nt][1], da1, d0));
            s1 = fmaf(c[mt][nt][2], sa0, fmaf(c[mt][nt][3], sa1, s1));
            d1 = fmaf(c[mt][nt][2], da0, fmaf(c[mt][nt][3], da1, d1));
        }
#pragma unroll
        for (int o = 1; o <= 2; o <<= 1) {
            s0 += __shfl_xor_sync(0xffffffffu, s0, o);
            d0 += __shfl_xor_sync(0xffffffffu, d0, o);
            s1 += __shfl_xor_sync(0xffffffffu, s1, o);
            d1 += __shfl_xor_sync(0xffffffffu, d1, o);
        }
        if (tid4 == 0) {
            atomicAdd(&s_sc[mloc0 * 2 + 0], s0);
            atomicAdd(&s_sc[mloc0 * 2 + 1], d0);
            atomicAdd(&s_sc[mloc1 * 2 + 0], s1);
            atomicAdd(&s_sc[mloc1 * 2 + 1], d1);
        }
        const int r0 = bm + mloc0;
        const int r1 = bm + mloc1;
#pragma unroll
        for (int nt = 0; nt < 4; nt++) {
            const int col = head * 128 + warp_n * 32 + nt * 8 + 2 * tid4;
            if (r0 < NNODES)
                *(float2*)&g_h[(size_t)r0 * NOUT + col] = make_float2(c[mt][nt][0], c[mt][nt][1]);
            if (r1 < NNODES)
                *(float2*)&g_h[(size_t)r1 * NOUT + col] = make_float2(c[mt][nt][2], c[mt][nt][3]);
        }
    }
    __syncthreads();
    if (tid < 128) {
        const int r = bm + tid;
        if (r < NNODES) {
            g_asrc[r * 4 + head] = s_sc[tid * 2 + 0];
            g_adst[r * 4 + head] = s_sc[tid * 2 + 1];
        }
    }
}

// ------------------------------------------------------------------
// CSR build
// ------------------------------------------------------------------
__global__ __launch_bounds__(256) void hist_kernel(const int* __restrict__ ei) {
    const int e = blockIdx.x * blockDim.x + threadIdx.x;
    if (e >= ETOT) return;
    const int dst = (e < NEDGES) ? ei[NEDGES + e] : (e - NEDGES);
    atomicAdd(&g_deg[dst], 1);
}

__global__ __launch_bounds__(256) void scan_kernel() {
    __shared__ int wsum[8];
    __shared__ int s_base;
    const int tid = threadIdx.x;
    const int lane = tid & 31;
    const int warp = tid >> 5;
    const int i = blockIdx.x * 256 + tid;

    const int d = (i < NNODES) ? g_deg[i] : 0;
    int v = d;
#pragma unroll
    for (int o = 1; o < 32; o <<= 1) {
        int t = __shfl_up_sync(0xffffffffu, v, o);
        if (lane >= o) v += t;
    }
    if (lane == 31) wsum[warp] = v;
    __syncthreads();
    if (tid == 0) {
        int run = 0;
#pragma unroll
        for (int w = 0; w < 8; w++) { int t = wsum[w]; wsum[w] = run; run += t; }
        s_base = atomicAdd(&g_total, run);
    }
    __syncthreads();
    if (i < NNODES) {
        const int excl = s_base + wsum[warp] + v - d;
        g_start[i] = excl;
        g_work[i] = excl;
    }
}

__global__ __launch_bounds__(256) void scatter_kernel(const int* __restrict__ ei) {
    const int e = blockIdx.x * blockDim.x + threadIdx.x;
    if (e >= ETOT) return;
    int src, dst;
    if (e < NEDGES) { src = ei[e]; dst = ei[NEDGES + e]; }
    else { src = dst = e - NEDGES; }
    const int pos = atomicAdd(&g_work[dst], 1);
    g_csr[pos] = src;
}

// ------------------------------------------------------------------
// softmax: one warp per dst node (all 4 heads)
// ------------------------------------------------------------------
__global__ __launch_bounds__(256) void softmax_kernel() {
    const int gw = blockIdx.x * 8 + (threadIdx.x >> 5);
    const int lane = threadIdx.x & 31;
    if (gw >= NNODES) return;

    const int start = g_start[gw];
    const int deg = g_deg[gw];
    const float4 ad = *(const float4*)&g_adst[gw * 4];

    float4 mx = make_float4(-INFINITY, -INFINITY, -INFINITY, -INFINITY);
    for (int i = lane; i < deg; i += 32) {
        const int src = g_csr[start + i];
        const float4 as = *(const float4*)&g_asrc[src * 4];
        mx.x = fmaxf(mx.x, lrelu(as.x + ad.x));
        mx.y = fmaxf(mx.y, lrelu(as.y + ad.y));
        mx.z = fmaxf(mx.z, lrelu(as.z + ad.z));
        mx.w = fmaxf(mx.w, lrelu(as.w + ad.w));
    }
#pragma unroll
    for (int o = 16; o; o >>= 1) {
        mx.x = fmaxf(mx.x, __shfl_xor_sync(0xffffffffu, mx.x, o));
        mx.y = fmaxf(mx.y, __shfl_xor_sync(0xffffffffu, mx.y, o));
        mx.z = fmaxf(mx.z, __shfl_xor_sync(0xffffffffu, mx.z, o));
        mx.w = fmaxf(mx.w, __shfl_xor_sync(0xffffffffu, mx.w, o));
    }

    float4 sm = make_float4(0.f, 0.f, 0.f, 0.f);
    for (int i = lane; i < deg; i += 32) {
        const int src = g_csr[start + i];
        const float4 as = *(const float4*)&g_asrc[src * 4];
        float4 e;
        e.x = __expf(lrelu(as.x + ad.x) - mx.x);
        e.y = __expf(lrelu(as.y + ad.y) - mx.y);
        e.z = __expf(lrelu(as.z + ad.z) - mx.z);
        e.w = __expf(lrelu(as.w + ad.w) - mx.w);
        *(float4*)&g_eexp[(size_t)(start + i) * 4] = e;
        sm.x += e.x; sm.y += e.y; sm.z += e.z; sm.w += e.w;
    }
#pragma unroll
    for (int o = 16; o; o >>= 1) {
        sm.x += __shfl_xor_sync(0xffffffffu, sm.x, o);
        sm.y += __shfl_xor_sync(0xffffffffu, sm.y, o);
        sm.z += __shfl_xor_sync(0xffffffffu, sm.z, o);
        sm.w += __shfl_xor_sync(0xffffffffu, sm.w, o);
    }
    if (lane == 0) {
        float4 r;
        r.x = 1.0f / sm.x; r.y = 1.0f / sm.y; r.z = 1.0f / sm.z; r.w = 1.0f / sm.w;
        *(float4*)&g_rden[gw * 4] = r;
    }
}

// ------------------------------------------------------------------
// aggregation: one warp per (dst, head)
// ------------------------------------------------------------------
__global__ __launch_bounds__(256) void aggregate_kernel(const float* __restrict__ bias,
                                                        float* __restrict__ out) {
    const int gw = blockIdx.x * 8 + (threadIdx.x >> 5);
    const int lane = threadIdx.x & 31;
    if (gw >= NH) return;
    const int dst = gw >> 2;
    const int hd = gw & 3;

    const int start = g_start[dst];
    const int deg = g_deg[dst];
    const float invd = g_rden[dst * 4 + hd];

    float4 acc = make_float4(0.f, 0.f, 0.f, 0.f);
    for (int base = 0; base < deg; base += 32) {
        const int n = min(32, deg - base);
        int src_l = 0;
        float e_l = 0.f;
        if (lane < n) {
            src_l = g_csr[start + base + lane];
            e_l = g_eexp[(size_t)(start + base + lane) * 4 + hd];
        }
        for (int j = 0; j < n; j++) {
            const int src = __shfl_sync(0xffffffffu, src_l, j);
            const float al = __shfl_sync(0xffffffffu, e_l, j) * invd;
            const float4 hv = *(const float4*)&g_h[(size_t)src * NOUT + hd * CH + lane * 4];
            acc.x = fmaf(al, hv.x, acc.x);
            acc.y = fmaf(al, hv.y, acc.y);
            acc.z = fmaf(al, hv.z, acc.z);
            acc.w = fmaf(al, hv.w, acc.w);
        }
    }
    const float4 b = *(const float4*)&bias[hd * CH + lane * 4];
    acc.x += b.x; acc.y += b.y; acc.z += b.z; acc.w += b.w;
    *(float4*)&out[(size_t)dst * NOUT + hd * CH + lane * 4] = acc;
}

// ------------------------------------------------------------------
extern "C" void kernel_launch(void* const* d_in, const int* in_sizes, int n_in,
                              void* d_out, int out_size) {
    const float* x       = (const float*)d_in[0];
    const int* ei        = (const int*)d_in[1];
    const float* W       = (const float*)d_in[2];
    const float* att_src = (const float*)d_in[3];
    const float* att_dst = (const float*)d_in[4];
    const float* bias    = (const float*)d_in[5];
    float* out           = (float*)d_out;

    (void)in_sizes; (void)n_in; (void)out_size;

    cudaFuncSetAttribute(gemm_mma_kernel, cudaFuncAttributeMaxDynamicSharedMemorySize, SMEM_DYN);

    prep_kernel<<<(NXG + NWG + 255) / 256, 256>>>(x, W);
    {
        dim3 grid(MTILES, HEADS);
        gemm_mma_kernel<<<grid, 256, SMEM_DYN>>>(att_src, att_dst);
    }
    hist_kernel<<<(ETOT + 255) / 256, 256>>>(ei);
    scan_kernel<<<(NNODES + 255) / 256, 256>>>();
    scatter_kernel<<<(ETOT + 255) / 256, 256>>>(ei);
    softmax_kernel<<<(NNODES + 7) / 8, 256>>>();
    aggregate_kernel<<<(NH + 7) / 8, 256>>>(bias, out);
}